// round 15
// baseline (speedup 1.0000x reference)
#include <cuda_runtime.h>
#include <cuda_fp16.h>
#include <cstdint>
#include <cstddef>

#define CC   0.1f
#define SCc  0.31622776601683794f   /* sqrt(0.1) */
#define EPSc 1e-7f

#define Bd  64
#define Nd  1024
#define Dd  128
#define DX  129
#define NCd 10

// ---------------- warp-MMA / cp.async helpers (baseline PTX) ---------------
__device__ __forceinline__ uint32_t smem_u32(const void* p)
{
    uint32_t a;
    asm("{ .reg .u64 t; cvta.to.shared.u64 t, %1; cvt.u32.u64 %0, t; }"
        : "=r"(a) : "l"(p));
    return a;
}
__device__ __forceinline__ void ldsm4(uint32_t& r0, uint32_t& r1,
                                      uint32_t& r2, uint32_t& r3, uint32_t addr)
{
    asm volatile("ldmatrix.sync.aligned.m8n8.x4.shared.b16 {%0,%1,%2,%3}, [%4];"
                 : "=r"(r0), "=r"(r1), "=r"(r2), "=r"(r3) : "r"(addr));
}
__device__ __forceinline__ void ldsm4t(uint32_t& r0, uint32_t& r1,
                                       uint32_t& r2, uint32_t& r3, uint32_t addr)
{
    asm volatile("ldmatrix.sync.aligned.m8n8.x4.trans.shared.b16 {%0,%1,%2,%3}, [%4];"
                 : "=r"(r0), "=r"(r1), "=r"(r2), "=r"(r3) : "r"(addr));
}
__device__ __forceinline__ void mma16816(float* c, uint32_t a0, uint32_t a1,
                                         uint32_t a2, uint32_t a3,
                                         uint32_t b0, uint32_t b1)
{
    asm volatile("mma.sync.aligned.m16n8k16.row.col.f32.f16.f16.f32 "
                 "{%0,%1,%2,%3}, {%4,%5,%6,%7}, {%8,%9}, {%0,%1,%2,%3};"
                 : "+f"(c[0]), "+f"(c[1]), "+f"(c[2]), "+f"(c[3])
                 : "r"(a0), "r"(a1), "r"(a2), "r"(a3), "r"(b0), "r"(b1));
}
__device__ __forceinline__ void cpasync16(uint32_t dst, const void* src)
{
    asm volatile("cp.async.cg.shared.global [%0], [%1], 16;"
                 :: "r"(dst), "l"(src) : "memory");
}
__device__ __forceinline__ void cp_commit()
{
    asm volatile("cp.async.commit_group;" ::: "memory");
}
__device__ __forceinline__ void cp_wait0()
{
    asm volatile("cp.async.wait_group 0;" ::: "memory");
}
__device__ __forceinline__ void cp_wait1()
{
    asm volatile("cp.async.wait_group 1;" ::: "memory");
}
__device__ __forceinline__ uint32_t packh(float a, float b)
{
    __half ha = __float2half_rn(a), hb = __float2half_rn(b);
    return (uint32_t)__half_as_ushort(ha) | ((uint32_t)__half_as_ushort(hb) << 16);
}

// ---------------- scratch (device globals; no runtime allocation) ----------
__device__ __align__(16) __half g_xh[(size_t)Bd*Nd*Dd];  // x spatial hi
__device__ __align__(16) __half g_xl[(size_t)Bd*Nd*Dd];  // x spatial lo
__device__ __align__(16) float  g_x0[(size_t)Bd*Nd];     // x time component
__device__ __align__(16) __half g_wh[(size_t)Dd*Dd];     // Wo spatial hi
__device__ __align__(16) __half g_wl[(size_t)Dd*Dd];     // Wo spatial lo
__device__ __align__(16) float  g_wo0[Dd];               // Wo[:,0]
__device__ __align__(16) float g_y [(size_t)Bd*Nd*Dd];   // Poincare tokens
__device__ __align__(16) float g_y2[(size_t)Bd*Nd];      // |y|^2 per token
__device__ __align__(16) unsigned char g_mask[(size_t)Bd*Nd];
__device__ int g_is32;

// ---------------- kernel 0a: detect mask dtype -----------------------------
__global__ void k_detect(const uint4* __restrict__ m)
{
    __shared__ int found;
    if (threadIdx.x == 0) found = 0;
    __syncthreads();
    unsigned int acc = 0;
    for (int i = threadIdx.x; i < Bd*Nd/16; i += blockDim.x) {
        uint4 v = m[i];
        acc |= (v.x | v.y | v.z | v.w) & 0xFFFFFF00u;
    }
    if (acc) atomicOr(&found, 1);
    __syncthreads();
    if (threadIdx.x == 0) g_is32 = found ? 0 : 1;
}

// ---------------- kernel 0b: mask normalize + Wo split (merged) ------------
__global__ void k_prep(const void* __restrict__ m, const float* __restrict__ Wo)
{
    if (blockIdx.x < 256) {
        int i = blockIdx.x * 256 + threadIdx.x;
        unsigned char v;
        if (g_is32) v = (((const int*)m)[i] != 0);
        else        v = (((const unsigned char*)m)[i] != 0);
        g_mask[i] = v;
    } else {
        int idx = (blockIdx.x - 256) * 256 + threadIdx.x;
        if (idx >= Dd*Dd) return;
        int o = idx >> 7, k = idx & 127;
        float v = Wo[o*DX + (k+1)];
        __half h = __float2half_rn(v);
        g_wh[idx] = h;
        g_wl[idx] = __float2half_rn(v - __half2float(h));
        if (k == 0) g_wo0[o] = Wo[o*DX];
    }
}

// ---------------- kernel 1: embedding + Lorentz expmap0 (fp16 split out) ---
__global__ void k_embed(const int* __restrict__ tok, const float* __restrict__ emb)
{
    int gw   = (blockIdx.x * blockDim.x + threadIdx.x) >> 5;
    int lane = threadIdx.x & 31;
    if (gw >= Bd*Nd) return;
    int t = tok[gw];
    float4 v = *(const float4*)(emb + (size_t)t*Dd + lane*4);
    float ss = v.x*v.x + v.y*v.y + v.z*v.z + v.w*v.w;
    #pragma unroll
    for (int o = 16; o; o >>= 1) ss += __shfl_xor_sync(0xffffffffu, ss, o);
    float nv   = fmaxf(sqrtf(ss), EPSc);
    float tt   = SCc * nv;
    float coef = sinhf(tt) / (SCc * nv);
    if (lane == 0) g_x0[gw] = coshf(tt) / SCc;

    float vv[4] = {coef*v.x, coef*v.y, coef*v.z, coef*v.w};
    uint32_t h01, h23, l01, l23;
    {
        __half h0 = __float2half_rn(vv[0]), h1 = __float2half_rn(vv[1]);
        __half h2 = __float2half_rn(vv[2]), h3 = __float2half_rn(vv[3]);
        h01 = (uint32_t)__half_as_ushort(h0) | ((uint32_t)__half_as_ushort(h1) << 16);
        h23 = (uint32_t)__half_as_ushort(h2) | ((uint32_t)__half_as_ushort(h3) << 16);
        l01 = packh(vv[0] - __half2float(h0), vv[1] - __half2float(h1));
        l23 = packh(vv[2] - __half2float(h2), vv[3] - __half2float(h3));
    }
    uint2* ph = (uint2*)(g_xh + (size_t)gw*Dd + lane*4);
    uint2* pl = (uint2*)(g_xl + (size_t)gw*Dd + lane*4);
    *ph = make_uint2(h01, h23);
    *pl = make_uint2(l01, l23);
}

// ---------------- kernel 2: attention + FUSED projection via mma.sync ------
// (unchanged from R14: 3 CTAs/SM, staged waits, fused projection)
#define STX 136
#define OXIH  0
#define OXJH0 17408
#define OXJH1 34816
#define OXJL  52224
#define OX0I  69632
#define OX0J0 69888
#define OX0J1 70144
#define OMS0  70400
#define OMS1  70464
#define OWO0  70528
#define OBO   71040
#define ATT_SMEM 71552

__device__ __forceinline__ void prefetch_xjH(uint32_t sb, int b, int jt, int buf, int tid)
{
    size_t rowbase = (size_t)b*Nd + (size_t)jt*64;
    uint32_t dH = sb + (buf ? OXJH1 : OXJH0);
    #pragma unroll
    for (int c = 0; c < 8; c++) {
        int idx = tid + c*128;
        int row = idx >> 4, ch = idx & 15;
        cpasync16(dH + row*272 + ch*16, g_xh + (rowbase + row)*Dd + ch*8);
    }
    if (tid < 16) cpasync16(sb + (buf ? OX0J1 : OX0J0) + tid*16, g_x0 + rowbase + tid*4);
    if (tid < 4)  cpasync16(sb + (buf ? OMS1 : OMS0) + tid*16, g_mask + rowbase + tid*16);
    cp_commit();
}
__device__ __forceinline__ void prefetch_xjL(uint32_t sb, int b, int jt, int tid)
{
    size_t rowbase = (size_t)b*Nd + (size_t)jt*64;
    #pragma unroll
    for (int c = 0; c < 8; c++) {
        int idx = tid + c*128;
        int row = idx >> 4, ch = idx & 15;
        cpasync16(sb + OXJL + row*272 + ch*16, g_xl + (rowbase + row)*Dd + ch*8);
    }
    cp_commit();
}

__global__ void __launch_bounds__(128, 3) k_attn_mma(const float* __restrict__ bo)
{
    extern __shared__ float4 smem_f4[];
    char* smb = (char*)smem_f4;
    const uint32_t sb = smem_u32(smb);

    const int tid  = threadIdx.x;
    const int wid  = tid >> 5;
    const int lane = tid & 31;
    const int b    = blockIdx.y;
    const int i0   = blockIdx.x * 64;
    const float invsq = 1.0f / sqrtf(129.0f);

    {
        size_t rowbase = (size_t)b*Nd + i0;
        #pragma unroll
        for (int c = 0; c < 8; c++) {
            int idx = tid + c*128;
            int row = idx >> 4, ch = idx & 15;
            cpasync16(sb + OXIH + row*272 + ch*16, g_xh + (rowbase + row)*Dd + ch*8);
        }
        if (tid < 16)      cpasync16(sb + OX0I + tid*16, g_x0 + rowbase + tid*4);
        else if (tid < 48) cpasync16(sb + OWO0 + (tid-16)*16, g_wo0 + (tid-16)*4);
        else if (tid < 80) cpasync16(sb + OBO + (tid-48)*16, bo + (tid-48)*4);
    }
    prefetch_xjH(sb, b, 0, 0, tid);
    prefetch_xjL(sb, b, 0, tid);

    const int r0 = wid*16 + (lane >> 2);
    const int cq = (lane & 3) * 2;

    const int la_row = lane & 15;
    const int la_kof = (lane >> 4) << 3;
    const int lb_n   = (lane & 7) + ((lane >> 4) << 3);
    const int lb_kof = ((lane >> 3) & 1) << 3;
    const int tr_row = (lane & 7) + (((lane >> 3) & 1) << 3);
    const int tr_col = (lane >> 4) << 3;

    const uint32_t aXiH = sb + OXIH + ((wid*16 + la_row)*STX + la_kof)*2;

    float muc[16][4];
    #pragma unroll
    for (int f = 0; f < 16; f++)
        muc[f][0] = muc[f][1] = muc[f][2] = muc[f][3] = 0.f;
    float den0 = 0.f, den1 = 0.f, ac00 = 0.f, ac01 = 0.f;
    float xi0 = 0.f, xi1 = 0.f;

    int buf = 0;
    for (int jt = 0; jt < 16; jt++) {
        cp_wait1();
        __syncthreads();
        if (jt == 0) {
            xi0 = ((float*)(smb + OX0I))[r0];
            xi1 = ((float*)(smb + OX0I))[r0 + 8];
        }
        if (jt + 1 < 16) prefetch_xjH(sb, b, jt + 1, buf ^ 1, tid);

        const uint32_t oXjH = sb + (buf ? OXJH1 : OXJH0);
        const float*   x0j  = (const float*)(smb + (buf ? OX0J1 : OX0J0));
        const unsigned char* msb = (const unsigned char*)(smb + (buf ? OMS1 : OMS0));

        const uint32_t bXjH = oXjH + (lb_n*STX + lb_kof)*2;
        const uint32_t tXjH = oXjH + (tr_row*STX + tr_col)*2;
        const uint32_t tXjL = sb + OXJL + (tr_row*STX + tr_col)*2;

        float c[8][4];
        #pragma unroll
        for (int q = 0; q < 8; q++)
            c[q][0] = c[q][1] = c[q][2] = c[q][3] = 0.f;

        #pragma unroll
        for (int kk = 0; kk < 8; kk++) {
            uint32_t a0, a1, a2, a3;
            ldsm4(a0, a1, a2, a3, aXiH + kk*32);
            #pragma unroll
            for (int nb = 0; nb < 4; nb++) {
                uint32_t bH0, bH1, bH2, bH3;
                ldsm4(bH0, bH1, bH2, bH3, bXjH + nb*(16*STX*2) + kk*32);
                mma16816(c[nb*2],   a0, a1, a2, a3, bH0, bH1);
                mma16816(c[nb*2+1], a0, a1, a2, a3, bH2, bH3);
            }
        }

        if (jt + 1 < 16) cp_wait1();
        else             cp_wait0();

        uint32_t eaH[4][4], eaL[4][4];
        #pragma unroll
        for (int q = 0; q < 8; q++) {
            int j0 = q*8 + cq;
            float xjx = x0j[j0], xjy = x0j[j0+1];
            float m0 = (float)msb[j0], m1 = (float)msb[j0+1];
            float e00 = m0 * __expf((xi0*xjx - c[q][0]) * invsq);
            float e01 = m1 * __expf((xi0*xjy - c[q][1]) * invsq);
            float e10 = m0 * __expf((xi1*xjx - c[q][2]) * invsq);
            float e11 = m1 * __expf((xi1*xjy - c[q][3]) * invsq);
            den0 += e00 + e01;  den1 += e10 + e11;
            ac00 += e00*xjx + e01*xjy;
            ac01 += e10*xjx + e11*xjy;
            __half h00 = __float2half_rn(e00), h01 = __float2half_rn(e01);
            __half h10 = __float2half_rn(e10), h11 = __float2half_rn(e11);
            uint32_t hp0 = (uint32_t)__half_as_ushort(h00) | ((uint32_t)__half_as_ushort(h01) << 16);
            uint32_t hp1 = (uint32_t)__half_as_ushort(h10) | ((uint32_t)__half_as_ushort(h11) << 16);
            uint32_t lp0 = packh(e00 - __half2float(h00), e01 - __half2float(h01));
            uint32_t lp1 = packh(e10 - __half2float(h10), e11 - __half2float(h11));
            int kk = q >> 1;
            if ((q & 1) == 0) {
                eaH[kk][0] = hp0; eaH[kk][1] = hp1;
                eaL[kk][0] = lp0; eaL[kk][1] = lp1;
            } else {
                eaH[kk][2] = hp0; eaH[kk][3] = hp1;
                eaL[kk][2] = lp0; eaL[kk][3] = lp1;
            }
        }

        #pragma unroll
        for (int kk = 0; kk < 4; kk++) {
            #pragma unroll
            for (int nb = 0; nb < 8; nb++) {
                uint32_t bH0, bH1, bH2, bH3, bL0, bL1, bL2, bL3;
                ldsm4t(bH0, bH1, bH2, bH3, tXjH + (kk*16*STX + nb*16)*2);
                ldsm4t(bL0, bL1, bL2, bL3, tXjL + (kk*16*STX + nb*16)*2);
                mma16816(muc[nb*2],   eaH[kk][0], eaH[kk][1], eaH[kk][2], eaH[kk][3], bH0, bH1);
                mma16816(muc[nb*2+1], eaH[kk][0], eaH[kk][1], eaH[kk][2], eaH[kk][3], bH2, bH3);
                mma16816(muc[nb*2],   eaH[kk][0], eaH[kk][1], eaH[kk][2], eaH[kk][3], bL0, bL1);
                mma16816(muc[nb*2+1], eaH[kk][0], eaH[kk][1], eaH[kk][2], eaH[kk][3], bL2, bL3);
                mma16816(muc[nb*2],   eaL[kk][0], eaL[kk][1], eaL[kk][2], eaL[kk][3], bH0, bH1);
                mma16816(muc[nb*2+1], eaL[kk][0], eaL[kk][1], eaL[kk][2], eaL[kk][3], bH2, bH3);
            }
        }

        __syncthreads();
        if (jt + 1 < 16) prefetch_xjL(sb, b, jt + 1, tid);
        buf ^= 1;
    }

    #pragma unroll
    for (int o = 1; o < 4; o <<= 1) {
        den0 += __shfl_xor_sync(0xffffffffu, den0, o);
        den1 += __shfl_xor_sync(0xffffffffu, den1, o);
        ac00 += __shfl_xor_sync(0xffffffffu, ac00, o);
        ac01 += __shfl_xor_sync(0xffffffffu, ac01, o);
    }
    float id0 = 1.f / den0, id1 = 1.f / den1;
    float mu00 = ac00 * id0, mu01 = ac01 * id1;

    float in0 = 0.f, in1 = 0.f;
    #pragma unroll
    for (int f = 0; f < 16; f++) {
        muc[f][0] *= id0; muc[f][1] *= id0;
        muc[f][2] *= id1; muc[f][3] *= id1;
        in0 += muc[f][0]*muc[f][0] + muc[f][1]*muc[f][1];
        in1 += muc[f][2]*muc[f][2] + muc[f][3]*muc[f][3];
    }
    #pragma unroll
    for (int o = 1; o < 4; o <<= 1) {
        in0 += __shfl_xor_sync(0xffffffffu, in0, o);
        in1 += __shfl_xor_sync(0xffffffffu, in1, o);
    }
    float s20 = 1.f / (SCc * sqrtf(fmaxf(mu00*mu00 - in0, EPSc)));
    float s21 = 1.f / (SCc * sqrtf(fmaxf(mu01*mu01 - in1, EPSc)));
    float mu0a = mu00 * s20, mu0b = mu01 * s21;

    __syncthreads();
    #pragma unroll
    for (int c = 0; c < 16; c++) {
        int idx = tid + c*128;
        int row = idx >> 4, ch = idx & 15;
        cpasync16(sb + 0 + row*272 + ch*16, g_wh + (size_t)row*Dd + ch*8);
    }
    #pragma unroll
    for (int c = 0; c < 16; c++) {
        int idx = tid + c*128;
        int row = idx >> 4, ch = idx & 15;
        cpasync16(sb + 34816 + row*272 + ch*16, g_wl + (size_t)row*Dd + ch*8);
    }
    cp_commit();

    #pragma unroll
    for (int f = 0; f < 16; f++) {
        muc[f][0] *= s20; muc[f][1] *= s20;
        muc[f][2] *= s21; muc[f][3] *= s21;
    }
    uint32_t mAH[8][4], mAL[8][4];
    #pragma unroll
    for (int kk = 0; kk < 8; kk++) {
        #pragma unroll
        for (int g = 0; g < 2; g++) {
            int f = 2*kk + g;
            __half h0 = __float2half_rn(muc[f][0]), h1 = __float2half_rn(muc[f][1]);
            __half h2 = __float2half_rn(muc[f][2]), h3 = __float2half_rn(muc[f][3]);
            mAH[kk][2*g+0] = (uint32_t)__half_as_ushort(h0) | ((uint32_t)__half_as_ushort(h1) << 16);
            mAH[kk][2*g+1] = (uint32_t)__half_as_ushort(h2) | ((uint32_t)__half_as_ushort(h3) << 16);
            mAL[kk][2*g+0] = packh(muc[f][0] - __half2float(h0), muc[f][1] - __half2float(h1));
            mAL[kk][2*g+1] = packh(muc[f][2] - __half2float(h2), muc[f][3] - __half2float(h3));
        }
    }

    cp_wait0();
    __syncthreads();

    const uint32_t bWH = sb + 0     + (lb_n*STX + lb_kof)*2;
    const uint32_t bWL = sb + 34816 + (lb_n*STX + lb_kof)*2;

    float c2[16][4];
    #pragma unroll
    for (int q = 0; q < 16; q++)
        c2[q][0] = c2[q][1] = c2[q][2] = c2[q][3] = 0.f;

    #pragma unroll
    for (int kk = 0; kk < 8; kk++) {
        #pragma unroll
        for (int nb = 0; nb < 8; nb++) {
            uint32_t bH0, bH1, bH2, bH3, bL0, bL1, bL2, bL3;
            ldsm4(bH0, bH1, bH2, bH3, bWH + nb*(16*STX*2) + kk*32);
            ldsm4(bL0, bL1, bL2, bL3, bWL + nb*(16*STX*2) + kk*32);
            mma16816(c2[nb*2],   mAH[kk][0], mAH[kk][1], mAH[kk][2], mAH[kk][3], bH0, bH1);
            mma16816(c2[nb*2+1], mAH[kk][0], mAH[kk][1], mAH[kk][2], mAH[kk][3], bH2, bH3);
            mma16816(c2[nb*2],   mAH[kk][0], mAH[kk][1], mAH[kk][2], mAH[kk][3], bL0, bL1);
            mma16816(c2[nb*2+1], mAH[kk][0], mAH[kk][1], mAH[kk][2], mAH[kk][3], bL2, bL3);
            mma16816(c2[nb*2],   mAL[kk][0], mAL[kk][1], mAL[kk][2], mAL[kk][3], bH0, bH1);
            mma16816(c2[nb*2+1], mAL[kk][0], mAL[kk][1], mAL[kk][2], mAL[kk][3], bH2, bH3);
        }
    }

    const float* wo0s = (const float*)(smb + OWO0);
    const float* bos  = (const float*)(smb + OBO);

    float u[16][4];
    float pp0 = 0.f, pp1 = 0.f;
    #pragma unroll
    for (int q = 0; q < 16; q++) {
        int col = q*8 + cq;
        float w0 = wo0s[col], w1 = wo0s[col+1];
        float b0 = bos[col],  b1 = bos[col+1];
        u[q][0] = c2[q][0] + mu0a*w0 + b0;
        u[q][1] = c2[q][1] + mu0a*w1 + b1;
        u[q][2] = c2[q][2] + mu0b*w0 + b0;
        u[q][3] = c2[q][3] + mu0b*w1 + b1;
        pp0 += u[q][0]*u[q][0] + u[q][1]*u[q][1];
        pp1 += u[q][2]*u[q][2] + u[q][3]*u[q][3];
    }
    #pragma unroll
    for (int o = 1; o < 4; o <<= 1) {
        pp0 += __shfl_xor_sync(0xffffffffu, pp0, o);
        pp1 += __shfl_xor_sync(0xffffffffu, pp1, o);
    }
    float nu0 = fmaxf(sqrtf(pp0), EPSc);
    float nu1 = fmaxf(sqrtf(pp1), EPSc);
    float f0 = tanhf(SCc*nu0) / (SCc*nu0);
    float f1 = tanhf(SCc*nu1) / (SCc*nu1);

    float* y0 = g_y + ((size_t)b*Nd + i0 + r0) * Dd;
    float* y1 = y0 + (size_t)8 * Dd;
    float qq0 = 0.f, qq1 = 0.f;
    #pragma unroll
    for (int q = 0; q < 16; q++) {
        int col = q*8 + cq;
        float v00 = u[q][0]*f0, v01 = u[q][1]*f0;
        float v10 = u[q][2]*f1, v11 = u[q][3]*f1;
        *(float2*)(y0 + col) = make_float2(v00, v01);
        *(float2*)(y1 + col) = make_float2(v10, v11);
        qq0 += v00*v00 + v01*v01;
        qq1 += v10*v10 + v11*v11;
    }
    #pragma unroll
    for (int o = 1; o < 4; o <<= 1) {
        qq0 += __shfl_xor_sync(0xffffffffu, qq0, o);
        qq1 += __shfl_xor_sync(0xffffffffu, qq1, o);
    }
    if ((lane & 3) == 0) {
        g_y2[(size_t)b*Nd + i0 + r0]     = qq0;
        g_y2[(size_t)b*Nd + i0 + r0 + 8] = qq1;
    }
}

// ---------------- kernel 4: Mobius pooling + MLR head ----------------------
// 16-lane layout (8 dims/lane, upper half mirrors lower): 4 shfl rounds.
// One reciprocal per step instead of per-element division.
// Chunk-4 double-buffered register prefetch.
__global__ void k_pool(const float* __restrict__ Wf,
                       const float* __restrict__ bf,
                       float* __restrict__ out)
{
    const int b    = blockIdx.x;
    const int lane = threadIdx.x;
    const int lg   = lane & 15;          // lane group index (dims lg*8..lg*8+7)
    const float* yb  = g_y  + (size_t)b*Nd*Dd;
    const float* y2b = g_y2 + (size_t)b*Nd;
    const unsigned char* mb = g_mask + (size_t)b*Nd;

    float a[8];
    #pragma unroll
    for (int d = 0; d < 8; d++) a[d] = 0.f;
    int cnt = 0;

    float4 yB[2][4][2];
    float  y2B[2][4];
    uint32_t mB[2];

    // load chunk 0
    #pragma unroll
    for (int t = 0; t < 4; t++) {
        yB[0][t][0] = *(const float4*)(yb + (size_t)t*Dd + lg*8);
        yB[0][t][1] = *(const float4*)(yb + (size_t)t*Dd + lg*8 + 4);
    }
    {
        float4 q = *(const float4*)(y2b);
        y2B[0][0]=q.x; y2B[0][1]=q.y; y2B[0][2]=q.z; y2B[0][3]=q.w;
        mB[0] = *(const uint32_t*)(mb);
    }

    int cur = 0;
    for (int ch = 0; ch < Nd/4; ch++) {
        int nxt = cur ^ 1;
        if (ch + 1 < Nd/4) {
            const float* ybn = yb + (size_t)(ch+1)*4*Dd;
            #pragma unroll
            for (int t = 0; t < 4; t++) {
                yB[nxt][t][0] = *(const float4*)(ybn + (size_t)t*Dd + lg*8);
                yB[nxt][t][1] = *(const float4*)(ybn + (size_t)t*Dd + lg*8 + 4);
            }
            float4 q = *(const float4*)(y2b + (ch+1)*4);
            y2B[nxt][0]=q.x; y2B[nxt][1]=q.y; y2B[nxt][2]=q.z; y2B[nxt][3]=q.w;
            mB[nxt] = *(const uint32_t*)(mb + (ch+1)*4);
        }
        uint32_t m4 = mB[cur];
        #pragma unroll
        for (int t = 0; t < 4; t++) {
            if ((m4 >> (t*8)) & 0xFFu) {          // warp-uniform branch
                float4 v0 = yB[cur][t][0], v1 = yB[cur][t][1];
                float yy2 = y2B[cur][t];
                float xy = a[0]*v0.x + a[1]*v0.y + a[2]*v0.z + a[3]*v0.w
                         + a[4]*v1.x + a[5]*v1.y + a[6]*v1.z + a[7]*v1.w;
                float x2 = a[0]*a[0] + a[1]*a[1] + a[2]*a[2] + a[3]*a[3]
                         + a[4]*a[4] + a[5]*a[5] + a[6]*a[6] + a[7]*a[7];
                #pragma unroll
                for (int o = 8; o; o >>= 1) {     // 4 rounds within 16-group
                    xy += __shfl_xor_sync(0xffffffffu, xy, o);
                    x2 += __shfl_xor_sync(0xffffffffu, x2, o);
                }
                float aa  = 1.f + 2.f*CC*xy + CC*yy2;
                float bb  = 1.f - CC*x2;
                float den = fmaxf(1.f + 2.f*CC*xy + CC*CC*x2*yy2, 1e-12f);
                float r   = 1.f / den;
                a[0] = (aa*a[0] + bb*v0.x) * r;
                a[1] = (aa*a[1] + bb*v0.y) * r;
                a[2] = (aa*a[2] + bb*v0.z) * r;
                a[3] = (aa*a[3] + bb*v0.w) * r;
                a[4] = (aa*a[4] + bb*v1.x) * r;
                a[5] = (aa*a[5] + bb*v1.y) * r;
                a[6] = (aa*a[6] + bb*v1.z) * r;
                a[7] = (aa*a[7] + bb*v1.w) * r;
                cnt++;
            }
        }
        cur = nxt;
    }

    // mobius scalar-mul by 1/cnt
    float n2 = 0.f;
    #pragma unroll
    for (int d = 0; d < 8; d++) n2 += a[d]*a[d];
    #pragma unroll
    for (int o = 8; o; o >>= 1) n2 += __shfl_xor_sync(0xffffffffu, n2, o);
    float nrm = sqrtf(n2);
    float t   = fminf(fmaxf(SCc*nrm, EPSc), 1.f - 1e-6f);
    float rr  = 1.f / fmaxf((float)cnt, 1.f);
    float fac = tanhf(rr * atanhf(t)) / fmaxf(SCc*nrm, EPSc);
    float p[8];
    #pragma unroll
    for (int d = 0; d < 8; d++) p[d] = fac * a[d];
    if (cnt == 0) {
        float4 y0 = *(const float4*)(yb + lg*8);
        float4 y1 = *(const float4*)(yb + lg*8 + 4);
        p[0]=y0.x; p[1]=y0.y; p[2]=y0.z; p[3]=y0.w;
        p[4]=y1.x; p[5]=y1.y; p[6]=y1.z; p[7]=y1.w;
    }

    // logmap0
    float pn2 = 0.f;
    #pragma unroll
    for (int d = 0; d < 8; d++) pn2 += p[d]*p[d];
    #pragma unroll
    for (int o = 8; o; o >>= 1) pn2 += __shfl_xor_sync(0xffffffffu, pn2, o);
    float npn = fmaxf(sqrtf(pn2), EPSc);
    float t2  = fminf(fmaxf(SCc*npn, EPSc), 1.f - 1e-6f);
    float cf  = atanhf(t2) / (SCc*npn);
    float v[8];
    #pragma unroll
    for (int d = 0; d < 8; d++) v[d] = cf * p[d];

    // logits
    for (int k = 0; k < NCd; k++) {
        float4 w0 = *(const float4*)(Wf + (size_t)k*Dd + lg*8);
        float4 w1 = *(const float4*)(Wf + (size_t)k*Dd + lg*8 + 4);
        float pr = v[0]*w0.x + v[1]*w0.y + v[2]*w0.z + v[3]*w0.w
                 + v[4]*w1.x + v[5]*w1.y + v[6]*w1.z + v[7]*w1.w;
        #pragma unroll
        for (int o = 8; o; o >>= 1) pr += __shfl_xor_sync(0xffffffffu, pr, o);
        if (lane == 0) out[b*NCd + k] = pr + bf[k];
    }
}

// ---------------------------- launcher -------------------------------------
extern "C" void kernel_launch(void* const* d_in, const int* in_sizes, int n_in,
                              void* d_out, int out_size)
{
    (void)in_sizes; (void)n_in; (void)out_size;
    const int*   tok  = (const int*)d_in[0];
    const void*  mask = d_in[1];
    const float* emb  = (const float*)d_in[2];
    const float* Wo   = (const float*)d_in[3];
    const float* bo   = (const float*)d_in[4];
    const float* Wf   = (const float*)d_in[5];
    const float* bf   = (const float*)d_in[6];
    float*       out  = (float*)d_out;

    cudaFuncSetAttribute(k_attn_mma, cudaFuncAttributeMaxDynamicSharedMemorySize, ATT_SMEM);

    k_detect   <<<1, 1024>>>((const uint4*)mask);
    k_prep     <<<256 + (Dd*Dd + 255)/256, 256>>>(mask, Wo);
    k_embed    <<<(Bd*Nd)/8, 256>>>(tok, emb);
    k_attn_mma <<<dim3(16, Bd), 128, ATT_SMEM>>>(bo);
    k_pool     <<<Bd, 32>>>(Wf, bf, out);
}

// round 16
// speedup vs baseline: 1.0975x; 1.0975x over previous
#include <cuda_runtime.h>
#include <cuda_fp16.h>
#include <cstdint>
#include <cstddef>

#define CC   0.1f
#define SCc  0.31622776601683794f   /* sqrt(0.1) */
#define EPSc 1e-7f

#define Bd  64
#define Nd  1024
#define Dd  128
#define DX  129
#define NCd 10

// ---------------- warp-MMA / cp.async helpers (baseline PTX) ---------------
__device__ __forceinline__ uint32_t smem_u32(const void* p)
{
    uint32_t a;
    asm("{ .reg .u64 t; cvta.to.shared.u64 t, %1; cvt.u32.u64 %0, t; }"
        : "=r"(a) : "l"(p));
    return a;
}
__device__ __forceinline__ void ldsm4(uint32_t& r0, uint32_t& r1,
                                      uint32_t& r2, uint32_t& r3, uint32_t addr)
{
    asm volatile("ldmatrix.sync.aligned.m8n8.x4.shared.b16 {%0,%1,%2,%3}, [%4];"
                 : "=r"(r0), "=r"(r1), "=r"(r2), "=r"(r3) : "r"(addr));
}
__device__ __forceinline__ void ldsm4t(uint32_t& r0, uint32_t& r1,
                                       uint32_t& r2, uint32_t& r3, uint32_t addr)
{
    asm volatile("ldmatrix.sync.aligned.m8n8.x4.trans.shared.b16 {%0,%1,%2,%3}, [%4];"
                 : "=r"(r0), "=r"(r1), "=r"(r2), "=r"(r3) : "r"(addr));
}
__device__ __forceinline__ void mma16816(float* c, uint32_t a0, uint32_t a1,
                                         uint32_t a2, uint32_t a3,
                                         uint32_t b0, uint32_t b1)
{
    asm volatile("mma.sync.aligned.m16n8k16.row.col.f32.f16.f16.f32 "
                 "{%0,%1,%2,%3}, {%4,%5,%6,%7}, {%8,%9}, {%0,%1,%2,%3};"
                 : "+f"(c[0]), "+f"(c[1]), "+f"(c[2]), "+f"(c[3])
                 : "r"(a0), "r"(a1), "r"(a2), "r"(a3), "r"(b0), "r"(b1));
}
__device__ __forceinline__ void cpasync16(uint32_t dst, const void* src)
{
    asm volatile("cp.async.cg.shared.global [%0], [%1], 16;"
                 :: "r"(dst), "l"(src) : "memory");
}
__device__ __forceinline__ void cp_commit()
{
    asm volatile("cp.async.commit_group;" ::: "memory");
}
__device__ __forceinline__ void cp_wait0()
{
    asm volatile("cp.async.wait_group 0;" ::: "memory");
}
__device__ __forceinline__ void cp_wait1()
{
    asm volatile("cp.async.wait_group 1;" ::: "memory");
}
__device__ __forceinline__ uint32_t packh(float a, float b)
{
    __half2 h = __float22half2_rn(make_float2(a, b));
    return *(uint32_t*)&h;
}

// ---------------- scratch (device globals; no runtime allocation) ----------
__device__ __align__(16) __half g_xh[(size_t)Bd*Nd*Dd];  // x spatial hi
__device__ __align__(16) __half g_xl[(size_t)Bd*Nd*Dd];  // x spatial lo
__device__ __align__(16) float  g_x0[(size_t)Bd*Nd];     // x time component
__device__ __align__(16) __half g_wh[(size_t)Dd*Dd];     // Wo spatial hi
__device__ __align__(16) __half g_wl[(size_t)Dd*Dd];     // Wo spatial lo
__device__ __align__(16) float  g_wo0[Dd];               // Wo[:,0]
__device__ __align__(16) float g_y [(size_t)Bd*Nd*Dd];   // Poincare tokens
__device__ __align__(16) float g_y2[(size_t)Bd*Nd];      // |y|^2 per token
__device__ __align__(16) unsigned char g_mask[(size_t)Bd*Nd];
__device__ int g_is32;

// ---------------- kernel 0a: detect mask dtype -----------------------------
__global__ void k_detect(const uint4* __restrict__ m)
{
    __shared__ int found;
    if (threadIdx.x == 0) found = 0;
    __syncthreads();
    unsigned int acc = 0;
    for (int i = threadIdx.x; i < Bd*Nd/16; i += blockDim.x) {
        uint4 v = m[i];
        acc |= (v.x | v.y | v.z | v.w) & 0xFFFFFF00u;
    }
    if (acc) atomicOr(&found, 1);
    __syncthreads();
    if (threadIdx.x == 0) g_is32 = found ? 0 : 1;
}

// ---------------- kernel 0b: mask normalize + Wo split (merged) ------------
__global__ void k_prep(const void* __restrict__ m, const float* __restrict__ Wo)
{
    if (blockIdx.x < 256) {
        int i = blockIdx.x * 256 + threadIdx.x;
        unsigned char v;
        if (g_is32) v = (((const int*)m)[i] != 0);
        else        v = (((const unsigned char*)m)[i] != 0);
        g_mask[i] = v;
    } else {
        int idx = (blockIdx.x - 256) * 256 + threadIdx.x;
        if (idx >= Dd*Dd) return;
        int o = idx >> 7, k = idx & 127;
        float v = Wo[o*DX + (k+1)];
        __half h = __float2half_rn(v);
        g_wh[idx] = h;
        g_wl[idx] = __float2half_rn(v - __half2float(h));
        if (k == 0) g_wo0[o] = Wo[o*DX];
    }
}

// ---------------- kernel 1: embedding + Lorentz expmap0 (fp16 split out) ---
__global__ void k_embed(const int* __restrict__ tok, const float* __restrict__ emb)
{
    int gw   = (blockIdx.x * blockDim.x + threadIdx.x) >> 5;
    int lane = threadIdx.x & 31;
    if (gw >= Bd*Nd) return;
    int t = tok[gw];
    float4 v = *(const float4*)(emb + (size_t)t*Dd + lane*4);
    float ss = v.x*v.x + v.y*v.y + v.z*v.z + v.w*v.w;
    #pragma unroll
    for (int o = 16; o; o >>= 1) ss += __shfl_xor_sync(0xffffffffu, ss, o);
    float nv   = fmaxf(sqrtf(ss), EPSc);
    float tt   = SCc * nv;
    float coef = sinhf(tt) / (SCc * nv);
    if (lane == 0) g_x0[gw] = coshf(tt) / SCc;

    float vv[4] = {coef*v.x, coef*v.y, coef*v.z, coef*v.w};
    uint32_t h01, h23, l01, l23;
    {
        __half h0 = __float2half_rn(vv[0]), h1 = __float2half_rn(vv[1]);
        __half h2 = __float2half_rn(vv[2]), h3 = __float2half_rn(vv[3]);
        h01 = (uint32_t)__half_as_ushort(h0) | ((uint32_t)__half_as_ushort(h1) << 16);
        h23 = (uint32_t)__half_as_ushort(h2) | ((uint32_t)__half_as_ushort(h3) << 16);
        l01 = packh(vv[0] - __half2float(h0), vv[1] - __half2float(h1));
        l23 = packh(vv[2] - __half2float(h2), vv[3] - __half2float(h3));
    }
    uint2* ph = (uint2*)(g_xh + (size_t)gw*Dd + lane*4);
    uint2* pl = (uint2*)(g_xl + (size_t)gw*Dd + lane*4);
    *ph = make_uint2(h01, h23);
    *pl = make_uint2(l01, l23);
}

// ---------------- kernel 2: attention + FUSED projection via mma.sync ------
// 3 CTAs/SM, staged waits, fused projection; packed f16x2 converts.
#define STX 136
#define OXIH  0
#define OXJH0 17408
#define OXJH1 34816
#define OXJL  52224
#define OX0I  69632
#define OX0J0 69888
#define OX0J1 70144
#define OMS0  70400
#define OMS1  70464
#define OWO0  70528
#define OBO   71040
#define ATT_SMEM 71552

__device__ __forceinline__ void prefetch_xjH(uint32_t sb, int b, int jt, int buf, int tid)
{
    size_t rowbase = (size_t)b*Nd + (size_t)jt*64;
    uint32_t dH = sb + (buf ? OXJH1 : OXJH0);
    #pragma unroll
    for (int c = 0; c < 8; c++) {
        int idx = tid + c*128;
        int row = idx >> 4, ch = idx & 15;
        cpasync16(dH + row*272 + ch*16, g_xh + (rowbase + row)*Dd + ch*8);
    }
    if (tid < 16) cpasync16(sb + (buf ? OX0J1 : OX0J0) + tid*16, g_x0 + rowbase + tid*4);
    if (tid < 4)  cpasync16(sb + (buf ? OMS1 : OMS0) + tid*16, g_mask + rowbase + tid*16);
    cp_commit();
}
__device__ __forceinline__ void prefetch_xjL(uint32_t sb, int b, int jt, int tid)
{
    size_t rowbase = (size_t)b*Nd + (size_t)jt*64;
    #pragma unroll
    for (int c = 0; c < 8; c++) {
        int idx = tid + c*128;
        int row = idx >> 4, ch = idx & 15;
        cpasync16(sb + OXJL + row*272 + ch*16, g_xl + (rowbase + row)*Dd + ch*8);
    }
    cp_commit();
}

__global__ void __launch_bounds__(128, 3) k_attn_mma(const float* __restrict__ bo)
{
    extern __shared__ float4 smem_f4[];
    char* smb = (char*)smem_f4;
    const uint32_t sb = smem_u32(smb);

    const int tid  = threadIdx.x;
    const int wid  = tid >> 5;
    const int lane = tid & 31;
    const int b    = blockIdx.y;
    const int i0   = blockIdx.x * 64;
    const float invsq = 1.0f / sqrtf(129.0f);

    {
        size_t rowbase = (size_t)b*Nd + i0;
        #pragma unroll
        for (int c = 0; c < 8; c++) {
            int idx = tid + c*128;
            int row = idx >> 4, ch = idx & 15;
            cpasync16(sb + OXIH + row*272 + ch*16, g_xh + (rowbase + row)*Dd + ch*8);
        }
        if (tid < 16)      cpasync16(sb + OX0I + tid*16, g_x0 + rowbase + tid*4);
        else if (tid < 48) cpasync16(sb + OWO0 + (tid-16)*16, g_wo0 + (tid-16)*4);
        else if (tid < 80) cpasync16(sb + OBO + (tid-48)*16, bo + (tid-48)*4);
    }
    prefetch_xjH(sb, b, 0, 0, tid);
    prefetch_xjL(sb, b, 0, tid);

    const int r0 = wid*16 + (lane >> 2);
    const int cq = (lane & 3) * 2;

    const int la_row = lane & 15;
    const int la_kof = (lane >> 4) << 3;
    const int lb_n   = (lane & 7) + ((lane >> 4) << 3);
    const int lb_kof = ((lane >> 3) & 1) << 3;
    const int tr_row = (lane & 7) + (((lane >> 3) & 1) << 3);
    const int tr_col = (lane >> 4) << 3;

    const uint32_t aXiH = sb + OXIH + ((wid*16 + la_row)*STX + la_kof)*2;

    float muc[16][4];
    #pragma unroll
    for (int f = 0; f < 16; f++)
        muc[f][0] = muc[f][1] = muc[f][2] = muc[f][3] = 0.f;
    float den0 = 0.f, den1 = 0.f, ac00 = 0.f, ac01 = 0.f;
    float xi0 = 0.f, xi1 = 0.f;

    int buf = 0;
    for (int jt = 0; jt < 16; jt++) {
        cp_wait1();
        __syncthreads();
        if (jt == 0) {
            xi0 = ((float*)(smb + OX0I))[r0];
            xi1 = ((float*)(smb + OX0I))[r0 + 8];
        }
        if (jt + 1 < 16) prefetch_xjH(sb, b, jt + 1, buf ^ 1, tid);

        const uint32_t oXjH = sb + (buf ? OXJH1 : OXJH0);
        const float*   x0j  = (const float*)(smb + (buf ? OX0J1 : OX0J0));
        const unsigned char* msb = (const unsigned char*)(smb + (buf ? OMS1 : OMS0));

        const uint32_t bXjH = oXjH + (lb_n*STX + lb_kof)*2;
        const uint32_t tXjH = oXjH + (tr_row*STX + tr_col)*2;
        const uint32_t tXjL = sb + OXJL + (tr_row*STX + tr_col)*2;

        float c[8][4];
        #pragma unroll
        for (int q = 0; q < 8; q++)
            c[q][0] = c[q][1] = c[q][2] = c[q][3] = 0.f;

        #pragma unroll
        for (int kk = 0; kk < 8; kk++) {
            uint32_t a0, a1, a2, a3;
            ldsm4(a0, a1, a2, a3, aXiH + kk*32);
            #pragma unroll
            for (int nb = 0; nb < 4; nb++) {
                uint32_t bH0, bH1, bH2, bH3;
                ldsm4(bH0, bH1, bH2, bH3, bXjH + nb*(16*STX*2) + kk*32);
                mma16816(c[nb*2],   a0, a1, a2, a3, bH0, bH1);
                mma16816(c[nb*2+1], a0, a1, a2, a3, bH2, bH3);
            }
        }

        if (jt + 1 < 16) cp_wait1();
        else             cp_wait0();

        uint32_t eaH[4][4], eaL[4][4];
        #pragma unroll
        for (int q = 0; q < 8; q++) {
            int j0 = q*8 + cq;
            float xjx = x0j[j0], xjy = x0j[j0+1];
            float m0 = (float)msb[j0], m1 = (float)msb[j0+1];
            float e00 = m0 * __expf((xi0*xjx - c[q][0]) * invsq);
            float e01 = m1 * __expf((xi0*xjy - c[q][1]) * invsq);
            float e10 = m0 * __expf((xi1*xjx - c[q][2]) * invsq);
            float e11 = m1 * __expf((xi1*xjy - c[q][3]) * invsq);
            den0 += e00 + e01;  den1 += e10 + e11;
            ac00 += e00*xjx + e01*xjy;
            ac01 += e10*xjx + e11*xjy;
            __half2 hA = __float22half2_rn(make_float2(e00, e01));
            __half2 hB = __float22half2_rn(make_float2(e10, e11));
            float2 fA = __half22float2(hA);
            float2 fB = __half22float2(hB);
            uint32_t hp0 = *(uint32_t*)&hA;
            uint32_t hp1 = *(uint32_t*)&hB;
            uint32_t lp0 = packh(e00 - fA.x, e01 - fA.y);
            uint32_t lp1 = packh(e10 - fB.x, e11 - fB.y);
            int kk = q >> 1;
            if ((q & 1) == 0) {
                eaH[kk][0] = hp0; eaH[kk][1] = hp1;
                eaL[kk][0] = lp0; eaL[kk][1] = lp1;
            } else {
                eaH[kk][2] = hp0; eaH[kk][3] = hp1;
                eaL[kk][2] = lp0; eaL[kk][3] = lp1;
            }
        }

        #pragma unroll
        for (int kk = 0; kk < 4; kk++) {
            #pragma unroll
            for (int nb = 0; nb < 8; nb++) {
                uint32_t bH0, bH1, bH2, bH3, bL0, bL1, bL2, bL3;
                ldsm4t(bH0, bH1, bH2, bH3, tXjH + (kk*16*STX + nb*16)*2);
                ldsm4t(bL0, bL1, bL2, bL3, tXjL + (kk*16*STX + nb*16)*2);
                mma16816(muc[nb*2],   eaH[kk][0], eaH[kk][1], eaH[kk][2], eaH[kk][3], bH0, bH1);
                mma16816(muc[nb*2+1], eaH[kk][0], eaH[kk][1], eaH[kk][2], eaH[kk][3], bH2, bH3);
                mma16816(muc[nb*2],   eaH[kk][0], eaH[kk][1], eaH[kk][2], eaH[kk][3], bL0, bL1);
                mma16816(muc[nb*2+1], eaH[kk][0], eaH[kk][1], eaH[kk][2], eaH[kk][3], bL2, bL3);
                mma16816(muc[nb*2],   eaL[kk][0], eaL[kk][1], eaL[kk][2], eaL[kk][3], bH0, bH1);
                mma16816(muc[nb*2+1], eaL[kk][0], eaL[kk][1], eaL[kk][2], eaL[kk][3], bH2, bH3);
            }
        }

        __syncthreads();
        if (jt + 1 < 16) prefetch_xjL(sb, b, jt + 1, tid);
        buf ^= 1;
    }

    #pragma unroll
    for (int o = 1; o < 4; o <<= 1) {
        den0 += __shfl_xor_sync(0xffffffffu, den0, o);
        den1 += __shfl_xor_sync(0xffffffffu, den1, o);
        ac00 += __shfl_xor_sync(0xffffffffu, ac00, o);
        ac01 += __shfl_xor_sync(0xffffffffu, ac01, o);
    }
    float id0 = 1.f / den0, id1 = 1.f / den1;
    float mu00 = ac00 * id0, mu01 = ac01 * id1;

    float in0 = 0.f, in1 = 0.f;
    #pragma unroll
    for (int f = 0; f < 16; f++) {
        muc[f][0] *= id0; muc[f][1] *= id0;
        muc[f][2] *= id1; muc[f][3] *= id1;
        in0 += muc[f][0]*muc[f][0] + muc[f][1]*muc[f][1];
        in1 += muc[f][2]*muc[f][2] + muc[f][3]*muc[f][3];
    }
    #pragma unroll
    for (int o = 1; o < 4; o <<= 1) {
        in0 += __shfl_xor_sync(0xffffffffu, in0, o);
        in1 += __shfl_xor_sync(0xffffffffu, in1, o);
    }
    float s20 = 1.f / (SCc * sqrtf(fmaxf(mu00*mu00 - in0, EPSc)));
    float s21 = 1.f / (SCc * sqrtf(fmaxf(mu01*mu01 - in1, EPSc)));
    float mu0a = mu00 * s20, mu0b = mu01 * s21;

    __syncthreads();
    #pragma unroll
    for (int c = 0; c < 16; c++) {
        int idx = tid + c*128;
        int row = idx >> 4, ch = idx & 15;
        cpasync16(sb + 0 + row*272 + ch*16, g_wh + (size_t)row*Dd + ch*8);
    }
    #pragma unroll
    for (int c = 0; c < 16; c++) {
        int idx = tid + c*128;
        int row = idx >> 4, ch = idx & 15;
        cpasync16(sb + 34816 + row*272 + ch*16, g_wl + (size_t)row*Dd + ch*8);
    }
    cp_commit();

    #pragma unroll
    for (int f = 0; f < 16; f++) {
        muc[f][0] *= s20; muc[f][1] *= s20;
        muc[f][2] *= s21; muc[f][3] *= s21;
    }
    uint32_t mAH[8][4], mAL[8][4];
    #pragma unroll
    for (int kk = 0; kk < 8; kk++) {
        #pragma unroll
        for (int g = 0; g < 2; g++) {
            int f = 2*kk + g;
            __half2 hA = __float22half2_rn(make_float2(muc[f][0], muc[f][1]));
            __half2 hB = __float22half2_rn(make_float2(muc[f][2], muc[f][3]));
            float2 fA = __half22float2(hA);
            float2 fB = __half22float2(hB);
            mAH[kk][2*g+0] = *(uint32_t*)&hA;
            mAH[kk][2*g+1] = *(uint32_t*)&hB;
            mAL[kk][2*g+0] = packh(muc[f][0] - fA.x, muc[f][1] - fA.y);
            mAL[kk][2*g+1] = packh(muc[f][2] - fB.x, muc[f][3] - fB.y);
        }
    }

    cp_wait0();
    __syncthreads();

    const uint32_t bWH = sb + 0     + (lb_n*STX + lb_kof)*2;
    const uint32_t bWL = sb + 34816 + (lb_n*STX + lb_kof)*2;

    float c2[16][4];
    #pragma unroll
    for (int q = 0; q < 16; q++)
        c2[q][0] = c2[q][1] = c2[q][2] = c2[q][3] = 0.f;

    #pragma unroll
    for (int kk = 0; kk < 8; kk++) {
        #pragma unroll
        for (int nb = 0; nb < 8; nb++) {
            uint32_t bH0, bH1, bH2, bH3, bL0, bL1, bL2, bL3;
            ldsm4(bH0, bH1, bH2, bH3, bWH + nb*(16*STX*2) + kk*32);
            ldsm4(bL0, bL1, bL2, bL3, bWL + nb*(16*STX*2) + kk*32);
            mma16816(c2[nb*2],   mAH[kk][0], mAH[kk][1], mAH[kk][2], mAH[kk][3], bH0, bH1);
            mma16816(c2[nb*2+1], mAH[kk][0], mAH[kk][1], mAH[kk][2], mAH[kk][3], bH2, bH3);
            mma16816(c2[nb*2],   mAH[kk][0], mAH[kk][1], mAH[kk][2], mAH[kk][3], bL0, bL1);
            mma16816(c2[nb*2+1], mAH[kk][0], mAH[kk][1], mAH[kk][2], mAH[kk][3], bL2, bL3);
            mma16816(c2[nb*2],   mAL[kk][0], mAL[kk][1], mAL[kk][2], mAL[kk][3], bH0, bH1);
            mma16816(c2[nb*2+1], mAL[kk][0], mAL[kk][1], mAL[kk][2], mAL[kk][3], bH2, bH3);
        }
    }

    const float* wo0s = (const float*)(smb + OWO0);
    const float* bos  = (const float*)(smb + OBO);

    float u[16][4];
    float pp0 = 0.f, pp1 = 0.f;
    #pragma unroll
    for (int q = 0; q < 16; q++) {
        int col = q*8 + cq;
        float w0 = wo0s[col], w1 = wo0s[col+1];
        float b0 = bos[col],  b1 = bos[col+1];
        u[q][0] = c2[q][0] + mu0a*w0 + b0;
        u[q][1] = c2[q][1] + mu0a*w1 + b1;
        u[q][2] = c2[q][2] + mu0b*w0 + b0;
        u[q][3] = c2[q][3] + mu0b*w1 + b1;
        pp0 += u[q][0]*u[q][0] + u[q][1]*u[q][1];
        pp1 += u[q][2]*u[q][2] + u[q][3]*u[q][3];
    }
    #pragma unroll
    for (int o = 1; o < 4; o <<= 1) {
        pp0 += __shfl_xor_sync(0xffffffffu, pp0, o);
        pp1 += __shfl_xor_sync(0xffffffffu, pp1, o);
    }
    float nu0 = fmaxf(sqrtf(pp0), EPSc);
    float nu1 = fmaxf(sqrtf(pp1), EPSc);
    float f0 = tanhf(SCc*nu0) / (SCc*nu0);
    float f1 = tanhf(SCc*nu1) / (SCc*nu1);

    float* y0 = g_y + ((size_t)b*Nd + i0 + r0) * Dd;
    float* y1 = y0 + (size_t)8 * Dd;
    float qq0 = 0.f, qq1 = 0.f;
    #pragma unroll
    for (int q = 0; q < 16; q++) {
        int col = q*8 + cq;
        float v00 = u[q][0]*f0, v01 = u[q][1]*f0;
        float v10 = u[q][2]*f1, v11 = u[q][3]*f1;
        *(float2*)(y0 + col) = make_float2(v00, v01);
        *(float2*)(y1 + col) = make_float2(v10, v11);
        qq0 += v00*v00 + v01*v01;
        qq1 += v10*v10 + v11*v11;
    }
    #pragma unroll
    for (int o = 1; o < 4; o <<= 1) {
        qq0 += __shfl_xor_sync(0xffffffffu, qq0, o);
        qq1 += __shfl_xor_sync(0xffffffffu, qq1, o);
    }
    if ((lane & 3) == 0) {
        g_y2[(size_t)b*Nd + i0 + r0]     = qq0;
        g_y2[(size_t)b*Nd + i0 + r0 + 8] = qq1;
    }
}

// ---------------- kernel 4: Mobius pooling + MLR head (R14 version) --------
// one warp per batch; chunks of 8 tokens, double-buffered register prefetch.
__global__ void k_pool(const float* __restrict__ Wf,
                       const float* __restrict__ bf,
                       float* __restrict__ out)
{
    const int b    = blockIdx.x;
    const int lane = threadIdx.x;
    const float* yb  = g_y  + (size_t)b*Nd*Dd;
    const float* y2b = g_y2 + (size_t)b*Nd;
    const unsigned char* mb = g_mask + (size_t)b*Nd;

    float a0=0.f, a1=0.f, a2=0.f, a3=0.f;
    int cnt = 0;

    float4 yB[2][8];
    float  y2B[2][8];
    unsigned long long mB[2];

    #pragma unroll
    for (int t = 0; t < 8; t++)
        yB[0][t] = *(const float4*)(yb + (size_t)t*Dd + lane*4);
    {
        float4 q0 = *(const float4*)(y2b + 0);
        float4 q1 = *(const float4*)(y2b + 4);
        y2B[0][0]=q0.x; y2B[0][1]=q0.y; y2B[0][2]=q0.z; y2B[0][3]=q0.w;
        y2B[0][4]=q1.x; y2B[0][5]=q1.y; y2B[0][6]=q1.z; y2B[0][7]=q1.w;
        mB[0] = *(const unsigned long long*)(mb);
    }

    int cur = 0;
    for (int ch = 0; ch < Nd/8; ch++) {
        int nxt = cur ^ 1;
        if (ch + 1 < Nd/8) {
            const float* ybn = yb + (size_t)(ch+1)*8*Dd;
            #pragma unroll
            for (int t = 0; t < 8; t++)
                yB[nxt][t] = *(const float4*)(ybn + (size_t)t*Dd + lane*4);
            float4 q0 = *(const float4*)(y2b + (ch+1)*8);
            float4 q1 = *(const float4*)(y2b + (ch+1)*8 + 4);
            y2B[nxt][0]=q0.x; y2B[nxt][1]=q0.y; y2B[nxt][2]=q0.z; y2B[nxt][3]=q0.w;
            y2B[nxt][4]=q1.x; y2B[nxt][5]=q1.y; y2B[nxt][6]=q1.z; y2B[nxt][7]=q1.w;
            mB[nxt] = *(const unsigned long long*)(mb + (ch+1)*8);
        }
        unsigned long long m8 = mB[cur];
        #pragma unroll
        for (int t = 0; t < 8; t++) {
            if ((m8 >> (t*8)) & 0xFFull) {
                float4 yv = yB[cur][t];
                float yy2 = y2B[cur][t];
                float xy = a0*yv.x + a1*yv.y + a2*yv.z + a3*yv.w;
                float x2 = a0*a0 + a1*a1 + a2*a2 + a3*a3;
                #pragma unroll
                for (int o = 16; o; o >>= 1) {
                    xy += __shfl_xor_sync(0xffffffffu, xy, o);
                    x2 += __shfl_xor_sync(0xffffffffu, x2, o);
                }
                float aa  = 1.f + 2.f*CC*xy + CC*yy2;
                float bb  = 1.f - CC*x2;
                float den = fmaxf(1.f + 2.f*CC*xy + CC*CC*x2*yy2, 1e-12f);
                a0 = (aa*a0 + bb*yv.x) / den;
                a1 = (aa*a1 + bb*yv.y) / den;
                a2 = (aa*a2 + bb*yv.z) / den;
                a3 = (aa*a3 + bb*yv.w) / den;
                cnt++;
            }
        }
        cur = nxt;
    }

    float n2 = a0*a0 + a1*a1 + a2*a2 + a3*a3;
    #pragma unroll
    for (int o = 16; o; o >>= 1) n2 += __shfl_xor_sync(0xffffffffu, n2, o);
    float nrm = sqrtf(n2);
    float t   = fminf(fmaxf(SCc*nrm, EPSc), 1.f - 1e-6f);
    float r   = 1.f / fmaxf((float)cnt, 1.f);
    float fac = tanhf(r * atanhf(t)) / fmaxf(SCc*nrm, EPSc);
    float p0 = fac*a0, p1 = fac*a1, p2 = fac*a2, p3 = fac*a3;
    if (cnt == 0) {
        float4 y0 = *(const float4*)(yb + lane*4);
        p0 = y0.x; p1 = y0.y; p2 = y0.z; p3 = y0.w;
    }

    float pn2 = p0*p0 + p1*p1 + p2*p2 + p3*p3;
    #pragma unroll
    for (int o = 16; o; o >>= 1) pn2 += __shfl_xor_sync(0xffffffffu, pn2, o);
    float npn = fmaxf(sqrtf(pn2), EPSc);
    float t2  = fminf(fmaxf(SCc*npn, EPSc), 1.f - 1e-6f);
    float cf  = atanhf(t2) / (SCc*npn);
    float v0 = cf*p0, v1 = cf*p1, v2 = cf*p2, v3 = cf*p3;

    for (int k = 0; k < NCd; k++) {
        float4 w = *(const float4*)(Wf + (size_t)k*Dd + lane*4);
        float pr = v0*w.x + v1*w.y + v2*w.z + v3*w.w;
        #pragma unroll
        for (int o = 16; o; o >>= 1) pr += __shfl_xor_sync(0xffffffffu, pr, o);
        if (lane == 0) out[b*NCd + k] = pr + bf[k];
    }
}

// ---------------------------- launcher -------------------------------------
extern "C" void kernel_launch(void* const* d_in, const int* in_sizes, int n_in,
                              void* d_out, int out_size)
{
    (void)in_sizes; (void)n_in; (void)out_size;
    const int*   tok  = (const int*)d_in[0];
    const void*  mask = d_in[1];
    const float* emb  = (const float*)d_in[2];
    const float* Wo   = (const float*)d_in[3];
    const float* bo   = (const float*)d_in[4];
    const float* Wf   = (const float*)d_in[5];
    const float* bf   = (const float*)d_in[6];
    float*       out  = (float*)d_out;

    cudaFuncSetAttribute(k_attn_mma, cudaFuncAttributeMaxDynamicSharedMemorySize, ATT_SMEM);

    k_detect   <<<1, 1024>>>((const uint4*)mask);
    k_prep     <<<256 + (Dd*Dd + 255)/256, 256>>>(mask, Wo);
    k_embed    <<<(Bd*Nd)/8, 256>>>(tok, emb);
    k_attn_mma <<<dim3(16, Bd), 128, ATT_SMEM>>>(bo);
    k_pool     <<<Bd, 32>>>(Wf, bf, out);
}

// round 17
// speedup vs baseline: 1.1514x; 1.0491x over previous
#include <cuda_runtime.h>
#include <cuda_fp16.h>
#include <cstdint>
#include <cstddef>

#define CC   0.1f
#define SCc  0.31622776601683794f   /* sqrt(0.1) */
#define EPSc 1e-7f

#define Bd  64
#define Nd  1024
#define Dd  128
#define DX  129
#define NCd 10

// ---------------- warp-MMA / cp.async helpers (baseline PTX) ---------------
__device__ __forceinline__ uint32_t smem_u32(const void* p)
{
    uint32_t a;
    asm("{ .reg .u64 t; cvta.to.shared.u64 t, %1; cvt.u32.u64 %0, t; }"
        : "=r"(a) : "l"(p));
    return a;
}
__device__ __forceinline__ void ldsm4(uint32_t& r0, uint32_t& r1,
                                      uint32_t& r2, uint32_t& r3, uint32_t addr)
{
    asm volatile("ldmatrix.sync.aligned.m8n8.x4.shared.b16 {%0,%1,%2,%3}, [%4];"
                 : "=r"(r0), "=r"(r1), "=r"(r2), "=r"(r3) : "r"(addr));
}
__device__ __forceinline__ void ldsm4t(uint32_t& r0, uint32_t& r1,
                                       uint32_t& r2, uint32_t& r3, uint32_t addr)
{
    asm volatile("ldmatrix.sync.aligned.m8n8.x4.trans.shared.b16 {%0,%1,%2,%3}, [%4];"
                 : "=r"(r0), "=r"(r1), "=r"(r2), "=r"(r3) : "r"(addr));
}
__device__ __forceinline__ void mma16816(float* c, uint32_t a0, uint32_t a1,
                                         uint32_t a2, uint32_t a3,
                                         uint32_t b0, uint32_t b1)
{
    asm volatile("mma.sync.aligned.m16n8k16.row.col.f32.f16.f16.f32 "
                 "{%0,%1,%2,%3}, {%4,%5,%6,%7}, {%8,%9}, {%0,%1,%2,%3};"
                 : "+f"(c[0]), "+f"(c[1]), "+f"(c[2]), "+f"(c[3])
                 : "r"(a0), "r"(a1), "r"(a2), "r"(a3), "r"(b0), "r"(b1));
}
__device__ __forceinline__ void cpasync16(uint32_t dst, const void* src)
{
    asm volatile("cp.async.cg.shared.global [%0], [%1], 16;"
                 :: "r"(dst), "l"(src) : "memory");
}
__device__ __forceinline__ void cp_commit()
{
    asm volatile("cp.async.commit_group;" ::: "memory");
}
__device__ __forceinline__ void cp_wait0()
{
    asm volatile("cp.async.wait_group 0;" ::: "memory");
}
__device__ __forceinline__ void cp_wait1()
{
    asm volatile("cp.async.wait_group 1;" ::: "memory");
}
__device__ __forceinline__ uint32_t packh(float a, float b)
{
    __half2 h = __float22half2_rn(make_float2(a, b));
    return *(uint32_t*)&h;
}

// ---------------- scratch (device globals; no runtime allocation) ----------
__device__ __align__(16) __half g_xh[(size_t)Bd*Nd*Dd];  // x spatial hi
__device__ __align__(16) __half g_xl[(size_t)Bd*Nd*Dd];  // x spatial lo
__device__ __align__(16) float  g_x0[(size_t)Bd*Nd];     // x time component
__device__ __align__(16) __half g_wh[(size_t)Dd*Dd];     // Wo spatial hi
__device__ __align__(16) __half g_wl[(size_t)Dd*Dd];     // Wo spatial lo
__device__ __align__(16) float  g_wo0[Dd];               // Wo[:,0]
__device__ __align__(16) float g_y [(size_t)Bd*Nd*Dd];   // Poincare tokens
__device__ __align__(16) float g_y2[(size_t)Bd*Nd];      // |y|^2 per token
__device__ __align__(16) float g_py[(size_t)Bd*(Nd/2)];  // <y_2t, y_2t+1>
__device__ __align__(16) unsigned char g_mask[(size_t)Bd*Nd];
__device__ int g_is32;

// ---------------- kernel 0a: detect mask dtype -----------------------------
__global__ void k_detect(const uint4* __restrict__ m)
{
    __shared__ int found;
    if (threadIdx.x == 0) found = 0;
    __syncthreads();
    unsigned int acc = 0;
    for (int i = threadIdx.x; i < Bd*Nd/16; i += blockDim.x) {
        uint4 v = m[i];
        acc |= (v.x | v.y | v.z | v.w) & 0xFFFFFF00u;
    }
    if (acc) atomicOr(&found, 1);
    __syncthreads();
    if (threadIdx.x == 0) g_is32 = found ? 0 : 1;
}

// ---------------- kernel 0b: mask normalize + Wo split (merged) ------------
__global__ void k_prep(const void* __restrict__ m, const float* __restrict__ Wo)
{
    if (blockIdx.x < 256) {
        int i = blockIdx.x * 256 + threadIdx.x;
        unsigned char v;
        if (g_is32) v = (((const int*)m)[i] != 0);
        else        v = (((const unsigned char*)m)[i] != 0);
        g_mask[i] = v;
    } else {
        int idx = (blockIdx.x - 256) * 256 + threadIdx.x;
        if (idx >= Dd*Dd) return;
        int o = idx >> 7, k = idx & 127;
        float v = Wo[o*DX + (k+1)];
        __half h = __float2half_rn(v);
        g_wh[idx] = h;
        g_wl[idx] = __float2half_rn(v - __half2float(h));
        if (k == 0) g_wo0[o] = Wo[o*DX];
    }
}

// ---------------- kernel 1: embedding + Lorentz expmap0 (fp16 split out) ---
__global__ void k_embed(const int* __restrict__ tok, const float* __restrict__ emb)
{
    int gw   = (blockIdx.x * blockDim.x + threadIdx.x) >> 5;
    int lane = threadIdx.x & 31;
    if (gw >= Bd*Nd) return;
    int t = tok[gw];
    float4 v = *(const float4*)(emb + (size_t)t*Dd + lane*4);
    float ss = v.x*v.x + v.y*v.y + v.z*v.z + v.w*v.w;
    #pragma unroll
    for (int o = 16; o; o >>= 1) ss += __shfl_xor_sync(0xffffffffu, ss, o);
    float nv   = fmaxf(sqrtf(ss), EPSc);
    float tt   = SCc * nv;
    float coef = sinhf(tt) / (SCc * nv);
    if (lane == 0) g_x0[gw] = coshf(tt) / SCc;

    float vv[4] = {coef*v.x, coef*v.y, coef*v.z, coef*v.w};
    uint32_t h01, h23, l01, l23;
    {
        __half h0 = __float2half_rn(vv[0]), h1 = __float2half_rn(vv[1]);
        __half h2 = __float2half_rn(vv[2]), h3 = __float2half_rn(vv[3]);
        h01 = (uint32_t)__half_as_ushort(h0) | ((uint32_t)__half_as_ushort(h1) << 16);
        h23 = (uint32_t)__half_as_ushort(h2) | ((uint32_t)__half_as_ushort(h3) << 16);
        l01 = packh(vv[0] - __half2float(h0), vv[1] - __half2float(h1));
        l23 = packh(vv[2] - __half2float(h2), vv[3] - __half2float(h3));
    }
    uint2* ph = (uint2*)(g_xh + (size_t)gw*Dd + lane*4);
    uint2* pl = (uint2*)(g_xl + (size_t)gw*Dd + lane*4);
    *ph = make_uint2(h01, h23);
    *pl = make_uint2(l01, l23);
}

// ---------------- kernel 2: attention + FUSED projection via mma.sync ------
#define STX 136
#define OXIH  0
#define OXJH0 17408
#define OXJH1 34816
#define OXJL  52224
#define OX0I  69632
#define OX0J0 69888
#define OX0J1 70144
#define OMS0  70400
#define OMS1  70464
#define OWO0  70528
#define OBO   71040
#define ATT_SMEM 71552

__device__ __forceinline__ void prefetch_xjH(uint32_t sb, int b, int jt, int buf, int tid)
{
    size_t rowbase = (size_t)b*Nd + (size_t)jt*64;
    uint32_t dH = sb + (buf ? OXJH1 : OXJH0);
    #pragma unroll
    for (int c = 0; c < 8; c++) {
        int idx = tid + c*128;
        int row = idx >> 4, ch = idx & 15;
        cpasync16(dH + row*272 + ch*16, g_xh + (rowbase + row)*Dd + ch*8);
    }
    if (tid < 16) cpasync16(sb + (buf ? OX0J1 : OX0J0) + tid*16, g_x0 + rowbase + tid*4);
    if (tid < 4)  cpasync16(sb + (buf ? OMS1 : OMS0) + tid*16, g_mask + rowbase + tid*16);
    cp_commit();
}
__device__ __forceinline__ void prefetch_xjL(uint32_t sb, int b, int jt, int tid)
{
    size_t rowbase = (size_t)b*Nd + (size_t)jt*64;
    #pragma unroll
    for (int c = 0; c < 8; c++) {
        int idx = tid + c*128;
        int row = idx >> 4, ch = idx & 15;
        cpasync16(sb + OXJL + row*272 + ch*16, g_xl + (rowbase + row)*Dd + ch*8);
    }
    cp_commit();
}

__global__ void __launch_bounds__(128, 3) k_attn_mma(const float* __restrict__ bo)
{
    extern __shared__ float4 smem_f4[];
    char* smb = (char*)smem_f4;
    const uint32_t sb = smem_u32(smb);

    const int tid  = threadIdx.x;
    const int wid  = tid >> 5;
    const int lane = tid & 31;
    const int b    = blockIdx.y;
    const int i0   = blockIdx.x * 64;
    const float invsq = 1.0f / sqrtf(129.0f);

    {
        size_t rowbase = (size_t)b*Nd + i0;
        #pragma unroll
        for (int c = 0; c < 8; c++) {
            int idx = tid + c*128;
            int row = idx >> 4, ch = idx & 15;
            cpasync16(sb + OXIH + row*272 + ch*16, g_xh + (rowbase + row)*Dd + ch*8);
        }
        if (tid < 16)      cpasync16(sb + OX0I + tid*16, g_x0 + rowbase + tid*4);
        else if (tid < 48) cpasync16(sb + OWO0 + (tid-16)*16, g_wo0 + (tid-16)*4);
        else if (tid < 80) cpasync16(sb + OBO + (tid-48)*16, bo + (tid-48)*4);
    }
    prefetch_xjH(sb, b, 0, 0, tid);
    prefetch_xjL(sb, b, 0, tid);

    const int r0 = wid*16 + (lane >> 2);
    const int cq = (lane & 3) * 2;

    const int la_row = lane & 15;
    const int la_kof = (lane >> 4) << 3;
    const int lb_n   = (lane & 7) + ((lane >> 4) << 3);
    const int lb_kof = ((lane >> 3) & 1) << 3;
    const int tr_row = (lane & 7) + (((lane >> 3) & 1) << 3);
    const int tr_col = (lane >> 4) << 3;

    const uint32_t aXiH = sb + OXIH + ((wid*16 + la_row)*STX + la_kof)*2;

    float muc[16][4];
    #pragma unroll
    for (int f = 0; f < 16; f++)
        muc[f][0] = muc[f][1] = muc[f][2] = muc[f][3] = 0.f;
    float den0 = 0.f, den1 = 0.f, ac00 = 0.f, ac01 = 0.f;
    float xi0 = 0.f, xi1 = 0.f;

    int buf = 0;
    for (int jt = 0; jt < 16; jt++) {
        cp_wait1();
        __syncthreads();
        if (jt == 0) {
            xi0 = ((float*)(smb + OX0I))[r0];
            xi1 = ((float*)(smb + OX0I))[r0 + 8];
        }
        if (jt + 1 < 16) prefetch_xjH(sb, b, jt + 1, buf ^ 1, tid);

        const uint32_t oXjH = sb + (buf ? OXJH1 : OXJH0);
        const float*   x0j  = (const float*)(smb + (buf ? OX0J1 : OX0J0));
        const unsigned char* msb = (const unsigned char*)(smb + (buf ? OMS1 : OMS0));

        const uint32_t bXjH = oXjH + (lb_n*STX + lb_kof)*2;
        const uint32_t tXjH = oXjH + (tr_row*STX + tr_col)*2;
        const uint32_t tXjL = sb + OXJL + (tr_row*STX + tr_col)*2;

        float c[8][4];
        #pragma unroll
        for (int q = 0; q < 8; q++)
            c[q][0] = c[q][1] = c[q][2] = c[q][3] = 0.f;

        #pragma unroll
        for (int kk = 0; kk < 8; kk++) {
            uint32_t a0, a1, a2, a3;
            ldsm4(a0, a1, a2, a3, aXiH + kk*32);
            #pragma unroll
            for (int nb = 0; nb < 4; nb++) {
                uint32_t bH0, bH1, bH2, bH3;
                ldsm4(bH0, bH1, bH2, bH3, bXjH + nb*(16*STX*2) + kk*32);
                mma16816(c[nb*2],   a0, a1, a2, a3, bH0, bH1);
                mma16816(c[nb*2+1], a0, a1, a2, a3, bH2, bH3);
            }
        }

        if (jt + 1 < 16) cp_wait1();
        else             cp_wait0();

        uint32_t eaH[4][4], eaL[4][4];
        #pragma unroll
        for (int q = 0; q < 8; q++) {
            int j0 = q*8 + cq;
            float xjx = x0j[j0], xjy = x0j[j0+1];
            float m0 = (float)msb[j0], m1 = (float)msb[j0+1];
            float e00 = m0 * __expf((xi0*xjx - c[q][0]) * invsq);
            float e01 = m1 * __expf((xi0*xjy - c[q][1]) * invsq);
            float e10 = m0 * __expf((xi1*xjx - c[q][2]) * invsq);
            float e11 = m1 * __expf((xi1*xjy - c[q][3]) * invsq);
            den0 += e00 + e01;  den1 += e10 + e11;
            ac00 += e00*xjx + e01*xjy;
            ac01 += e10*xjx + e11*xjy;
            __half2 hA = __float22half2_rn(make_float2(e00, e01));
            __half2 hB = __float22half2_rn(make_float2(e10, e11));
            float2 fA = __half22float2(hA);
            float2 fB = __half22float2(hB);
            uint32_t hp0 = *(uint32_t*)&hA;
            uint32_t hp1 = *(uint32_t*)&hB;
            uint32_t lp0 = packh(e00 - fA.x, e01 - fA.y);
            uint32_t lp1 = packh(e10 - fB.x, e11 - fB.y);
            int kk = q >> 1;
            if ((q & 1) == 0) {
                eaH[kk][0] = hp0; eaH[kk][1] = hp1;
                eaL[kk][0] = lp0; eaL[kk][1] = lp1;
            } else {
                eaH[kk][2] = hp0; eaH[kk][3] = hp1;
                eaL[kk][2] = lp0; eaL[kk][3] = lp1;
            }
        }

        #pragma unroll
        for (int kk = 0; kk < 4; kk++) {
            #pragma unroll
            for (int nb = 0; nb < 8; nb++) {
                uint32_t bH0, bH1, bH2, bH3, bL0, bL1, bL2, bL3;
                ldsm4t(bH0, bH1, bH2, bH3, tXjH + (kk*16*STX + nb*16)*2);
                ldsm4t(bL0, bL1, bL2, bL3, tXjL + (kk*16*STX + nb*16)*2);
                mma16816(muc[nb*2],   eaH[kk][0], eaH[kk][1], eaH[kk][2], eaH[kk][3], bH0, bH1);
                mma16816(muc[nb*2+1], eaH[kk][0], eaH[kk][1], eaH[kk][2], eaH[kk][3], bH2, bH3);
                mma16816(muc[nb*2],   eaH[kk][0], eaH[kk][1], eaH[kk][2], eaH[kk][3], bL0, bL1);
                mma16816(muc[nb*2+1], eaH[kk][0], eaH[kk][1], eaH[kk][2], eaH[kk][3], bL2, bL3);
                mma16816(muc[nb*2],   eaL[kk][0], eaL[kk][1], eaL[kk][2], eaL[kk][3], bH0, bH1);
                mma16816(muc[nb*2+1], eaL[kk][0], eaL[kk][1], eaL[kk][2], eaL[kk][3], bH2, bH3);
            }
        }

        __syncthreads();
        if (jt + 1 < 16) prefetch_xjL(sb, b, jt + 1, tid);
        buf ^= 1;
    }

    #pragma unroll
    for (int o = 1; o < 4; o <<= 1) {
        den0 += __shfl_xor_sync(0xffffffffu, den0, o);
        den1 += __shfl_xor_sync(0xffffffffu, den1, o);
        ac00 += __shfl_xor_sync(0xffffffffu, ac00, o);
        ac01 += __shfl_xor_sync(0xffffffffu, ac01, o);
    }
    float id0 = 1.f / den0, id1 = 1.f / den1;
    float mu00 = ac00 * id0, mu01 = ac01 * id1;

    float in0 = 0.f, in1 = 0.f;
    #pragma unroll
    for (int f = 0; f < 16; f++) {
        muc[f][0] *= id0; muc[f][1] *= id0;
        muc[f][2] *= id1; muc[f][3] *= id1;
        in0 += muc[f][0]*muc[f][0] + muc[f][1]*muc[f][1];
        in1 += muc[f][2]*muc[f][2] + muc[f][3]*muc[f][3];
    }
    #pragma unroll
    for (int o = 1; o < 4; o <<= 1) {
        in0 += __shfl_xor_sync(0xffffffffu, in0, o);
        in1 += __shfl_xor_sync(0xffffffffu, in1, o);
    }
    float s20 = 1.f / (SCc * sqrtf(fmaxf(mu00*mu00 - in0, EPSc)));
    float s21 = 1.f / (SCc * sqrtf(fmaxf(mu01*mu01 - in1, EPSc)));
    float mu0a = mu00 * s20, mu0b = mu01 * s21;

    __syncthreads();
    #pragma unroll
    for (int c = 0; c < 16; c++) {
        int idx = tid + c*128;
        int row = idx >> 4, ch = idx & 15;
        cpasync16(sb + 0 + row*272 + ch*16, g_wh + (size_t)row*Dd + ch*8);
    }
    #pragma unroll
    for (int c = 0; c < 16; c++) {
        int idx = tid + c*128;
        int row = idx >> 4, ch = idx & 15;
        cpasync16(sb + 34816 + row*272 + ch*16, g_wl + (size_t)row*Dd + ch*8);
    }
    cp_commit();

    #pragma unroll
    for (int f = 0; f < 16; f++) {
        muc[f][0] *= s20; muc[f][1] *= s20;
        muc[f][2] *= s21; muc[f][3] *= s21;
    }
    uint32_t mAH[8][4], mAL[8][4];
    #pragma unroll
    for (int kk = 0; kk < 8; kk++) {
        #pragma unroll
        for (int g = 0; g < 2; g++) {
            int f = 2*kk + g;
            __half2 hA = __float22half2_rn(make_float2(muc[f][0], muc[f][1]));
            __half2 hB = __float22half2_rn(make_float2(muc[f][2], muc[f][3]));
            float2 fA = __half22float2(hA);
            float2 fB = __half22float2(hB);
            mAH[kk][2*g+0] = *(uint32_t*)&hA;
            mAH[kk][2*g+1] = *(uint32_t*)&hB;
            mAL[kk][2*g+0] = packh(muc[f][0] - fA.x, muc[f][1] - fA.y);
            mAL[kk][2*g+1] = packh(muc[f][2] - fB.x, muc[f][3] - fB.y);
        }
    }

    cp_wait0();
    __syncthreads();

    const uint32_t bWH = sb + 0     + (lb_n*STX + lb_kof)*2;
    const uint32_t bWL = sb + 34816 + (lb_n*STX + lb_kof)*2;

    float c2[16][4];
    #pragma unroll
    for (int q = 0; q < 16; q++)
        c2[q][0] = c2[q][1] = c2[q][2] = c2[q][3] = 0.f;

    #pragma unroll
    for (int kk = 0; kk < 8; kk++) {
        #pragma unroll
        for (int nb = 0; nb < 8; nb++) {
            uint32_t bH0, bH1, bH2, bH3, bL0, bL1, bL2, bL3;
            ldsm4(bH0, bH1, bH2, bH3, bWH + nb*(16*STX*2) + kk*32);
            ldsm4(bL0, bL1, bL2, bL3, bWL + nb*(16*STX*2) + kk*32);
            mma16816(c2[nb*2],   mAH[kk][0], mAH[kk][1], mAH[kk][2], mAH[kk][3], bH0, bH1);
            mma16816(c2[nb*2+1], mAH[kk][0], mAH[kk][1], mAH[kk][2], mAH[kk][3], bH2, bH3);
            mma16816(c2[nb*2],   mAH[kk][0], mAH[kk][1], mAH[kk][2], mAH[kk][3], bL0, bL1);
            mma16816(c2[nb*2+1], mAH[kk][0], mAH[kk][1], mAH[kk][2], mAH[kk][3], bL2, bL3);
            mma16816(c2[nb*2],   mAL[kk][0], mAL[kk][1], mAL[kk][2], mAL[kk][3], bH0, bH1);
            mma16816(c2[nb*2+1], mAL[kk][0], mAL[kk][1], mAL[kk][2], mAL[kk][3], bH2, bH3);
        }
    }

    const float* wo0s = (const float*)(smb + OWO0);
    const float* bos  = (const float*)(smb + OBO);

    float u[16][4];
    float pp0 = 0.f, pp1 = 0.f;
    #pragma unroll
    for (int q = 0; q < 16; q++) {
        int col = q*8 + cq;
        float w0 = wo0s[col], w1 = wo0s[col+1];
        float b0 = bos[col],  b1 = bos[col+1];
        u[q][0] = c2[q][0] + mu0a*w0 + b0;
        u[q][1] = c2[q][1] + mu0a*w1 + b1;
        u[q][2] = c2[q][2] + mu0b*w0 + b0;
        u[q][3] = c2[q][3] + mu0b*w1 + b1;
        pp0 += u[q][0]*u[q][0] + u[q][1]*u[q][1];
        pp1 += u[q][2]*u[q][2] + u[q][3]*u[q][3];
    }
    #pragma unroll
    for (int o = 1; o < 4; o <<= 1) {
        pp0 += __shfl_xor_sync(0xffffffffu, pp0, o);
        pp1 += __shfl_xor_sync(0xffffffffu, pp1, o);
    }
    float nu0 = fmaxf(sqrtf(pp0), EPSc);
    float nu1 = fmaxf(sqrtf(pp1), EPSc);
    float f0 = tanhf(SCc*nu0) / (SCc*nu0);
    float f1 = tanhf(SCc*nu1) / (SCc*nu1);

    float* y0 = g_y + ((size_t)b*Nd + i0 + r0) * Dd;
    float* y1 = y0 + (size_t)8 * Dd;
    float qq0 = 0.f, qq1 = 0.f;
    #pragma unroll
    for (int q = 0; q < 16; q++) {
        int col = q*8 + cq;
        float v00 = u[q][0]*f0, v01 = u[q][1]*f0;
        float v10 = u[q][2]*f1, v11 = u[q][3]*f1;
        *(float2*)(y0 + col) = make_float2(v00, v01);
        *(float2*)(y1 + col) = make_float2(v10, v11);
        qq0 += v00*v00 + v01*v01;
        qq1 += v10*v10 + v11*v11;
    }
    #pragma unroll
    for (int o = 1; o < 4; o <<= 1) {
        qq0 += __shfl_xor_sync(0xffffffffu, qq0, o);
        qq1 += __shfl_xor_sync(0xffffffffu, qq1, o);
    }
    if ((lane & 3) == 0) {
        g_y2[(size_t)b*Nd + i0 + r0]     = qq0;
        g_y2[(size_t)b*Nd + i0 + r0 + 8] = qq1;
    }
}

// ---------------- kernel 3: pair dots <y_2t, y_2t+1> (off-chain) ------------
__global__ void k_pairdot()
{
    int blk  = blockIdx.x;            // Bd*16 blocks
    int b    = blk >> 4;
    int p0   = (blk & 15) * 32;
    int wid  = threadIdx.x >> 5;
    int lane = threadIdx.x & 31;
    const float* yb = g_y + (size_t)b*Nd*Dd;
    #pragma unroll
    for (int k = 0; k < 8; k++) {
        int pr = p0 + wid*8 + k;
        float4 u = *(const float4*)(yb + (size_t)(2*pr)*Dd + lane*4);
        float4 v = *(const float4*)(yb + (size_t)(2*pr+1)*Dd + lane*4);
        float d = u.x*v.x + u.y*v.y + u.z*v.z + u.w*v.w;
        #pragma unroll
        for (int o = 16; o; o >>= 1) d += __shfl_xor_sync(0xffffffffu, d, o);
        if (lane == 0) g_py[(size_t)b*(Nd/2) + pr] = d;
    }
}

// ---------------- kernel 4: Mobius pooling via PAIR folding + MLR head -----
// One warp per batch. Two Mobius adds collapsed into one reduce phase:
// reduce <a,y1>, <a,y2>, |a|^2 together; <y1,y2>, |y|^2 precomputed.
__global__ void k_pool(const float* __restrict__ Wf,
                       const float* __restrict__ bf,
                       float* __restrict__ out)
{
    const int b    = blockIdx.x;
    const int lane = threadIdx.x;
    const float* yb  = g_y  + (size_t)b*Nd*Dd;
    const float* y2b = g_y2 + (size_t)b*Nd;
    const float* pyb = g_py + (size_t)b*(Nd/2);
    const unsigned char* mb = g_mask + (size_t)b*Nd;

    float a0=0.f, a1=0.f, a2=0.f, a3=0.f;
    int cnt = 0;

    float4 yB[2][8];
    float  y2B[2][8];
    float  pyB[2][4];
    unsigned long long mB[2];

    #pragma unroll
    for (int t = 0; t < 8; t++)
        yB[0][t] = *(const float4*)(yb + (size_t)t*Dd + lane*4);
    {
        float4 q0 = *(const float4*)(y2b + 0);
        float4 q1 = *(const float4*)(y2b + 4);
        y2B[0][0]=q0.x; y2B[0][1]=q0.y; y2B[0][2]=q0.z; y2B[0][3]=q0.w;
        y2B[0][4]=q1.x; y2B[0][5]=q1.y; y2B[0][6]=q1.z; y2B[0][7]=q1.w;
        float4 pq = *(const float4*)(pyb);
        pyB[0][0]=pq.x; pyB[0][1]=pq.y; pyB[0][2]=pq.z; pyB[0][3]=pq.w;
        mB[0] = *(const unsigned long long*)(mb);
    }

    int cur = 0;
    for (int ch = 0; ch < Nd/8; ch++) {
        int nxt = cur ^ 1;
        if (ch + 1 < Nd/8) {
            const float* ybn = yb + (size_t)(ch+1)*8*Dd;
            #pragma unroll
            for (int t = 0; t < 8; t++)
                yB[nxt][t] = *(const float4*)(ybn + (size_t)t*Dd + lane*4);
            float4 q0 = *(const float4*)(y2b + (ch+1)*8);
            float4 q1 = *(const float4*)(y2b + (ch+1)*8 + 4);
            y2B[nxt][0]=q0.x; y2B[nxt][1]=q0.y; y2B[nxt][2]=q0.z; y2B[nxt][3]=q0.w;
            y2B[nxt][4]=q1.x; y2B[nxt][5]=q1.y; y2B[nxt][6]=q1.z; y2B[nxt][7]=q1.w;
            float4 pq = *(const float4*)(pyb + (ch+1)*4);
            pyB[nxt][0]=pq.x; pyB[nxt][1]=pq.y; pyB[nxt][2]=pq.z; pyB[nxt][3]=pq.w;
            mB[nxt] = *(const unsigned long long*)(mb + (ch+1)*8);
        }
        unsigned long long m8 = mB[cur];
        #pragma unroll
        for (int pp = 0; pp < 4; pp++) {
            int m1 = (int)((m8 >> (pp*16))     & 0xFFull);
            int m2 = (int)((m8 >> (pp*16 + 8)) & 0xFFull);
            if (!(m1 | m2)) continue;             // warp-uniform
            float4 v1 = yB[cur][2*pp];
            float4 v2 = yB[cur][2*pp+1];
            float q1v = y2B[cur][2*pp];
            float q2v = y2B[cur][2*pp+1];
            float p12 = pyB[cur][pp];

            float p1 = a0*v1.x + a1*v1.y + a2*v1.z + a3*v1.w;
            float p2 = a0*v2.x + a1*v2.y + a2*v2.z + a3*v2.w;
            float s  = a0*a0 + a1*a1 + a2*a2 + a3*a3;
            #pragma unroll
            for (int o = 16; o; o >>= 1) {
                p1 += __shfl_xor_sync(0xffffffffu, p1, o);
                p2 += __shfl_xor_sync(0xffffffffu, p2, o);
                s  += __shfl_xor_sync(0xffffffffu, s,  o);
            }

            if (m1 && m2) {
                float A1 = 1.f + 2.f*CC*p1 + CC*q1v;
                float B1 = 1.f - CC*s;
                float D1 = fmaxf(1.f + 2.f*CC*p1 + CC*CC*s*q1v, 1e-12f);
                float iD1 = 1.f / D1;
                float pb  = (A1*p2 + B1*p12) * iD1;
                float b2  = (A1*A1*s + 2.f*A1*B1*p1 + B1*B1*q1v) * (iD1*iD1);
                float A2 = 1.f + 2.f*CC*pb + CC*q2v;
                float B2 = 1.f - CC*b2;
                float D2 = fmaxf(1.f + 2.f*CC*pb + CC*CC*b2*q2v, 1e-12f);
                float iD2 = 1.f / D2;
                float Ka = A1*A2*iD1*iD2;
                float K1 = B1*A2*iD1*iD2;
                float K2 = B2*iD2;
                a0 = Ka*a0 + K1*v1.x + K2*v2.x;
                a1 = Ka*a1 + K1*v1.y + K2*v2.y;
                a2 = Ka*a2 + K1*v1.z + K2*v2.z;
                a3 = Ka*a3 + K1*v1.w + K2*v2.w;
                cnt += 2;
            } else if (m1) {
                float A = 1.f + 2.f*CC*p1 + CC*q1v;
                float B = 1.f - CC*s;
                float D = fmaxf(1.f + 2.f*CC*p1 + CC*CC*s*q1v, 1e-12f);
                a0 = (A*a0 + B*v1.x) / D;
                a1 = (A*a1 + B*v1.y) / D;
                a2 = (A*a2 + B*v1.z) / D;
                a3 = (A*a3 + B*v1.w) / D;
                cnt++;
            } else {
                float A = 1.f + 2.f*CC*p2 + CC*q2v;
                float B = 1.f - CC*s;
                float D = fmaxf(1.f + 2.f*CC*p2 + CC*CC*s*q2v, 1e-12f);
                a0 = (A*a0 + B*v2.x) / D;
                a1 = (A*a1 + B*v2.y) / D;
                a2 = (A*a2 + B*v2.z) / D;
                a3 = (A*a3 + B*v2.w) / D;
                cnt++;
            }
        }
        cur = nxt;
    }

    // mobius scalar-mul by 1/cnt
    float n2 = a0*a0 + a1*a1 + a2*a2 + a3*a3;
    #pragma unroll
    for (int o = 16; o; o >>= 1) n2 += __shfl_xor_sync(0xffffffffu, n2, o);
    float nrm = sqrtf(n2);
    float t   = fminf(fmaxf(SCc*nrm, EPSc), 1.f - 1e-6f);
    float r   = 1.f / fmaxf((float)cnt, 1.f);
    float fac = tanhf(r * atanhf(t)) / fmaxf(SCc*nrm, EPSc);
    float p0 = fac*a0, p1 = fac*a1, p2 = fac*a2, p3 = fac*a3;
    if (cnt == 0) {
        float4 y0 = *(const float4*)(yb + lane*4);
        p0 = y0.x; p1 = y0.y; p2 = y0.z; p3 = y0.w;
    }

    // logmap0
    float pn2 = p0*p0 + p1*p1 + p2*p2 + p3*p3;
    #pragma unroll
    for (int o = 16; o; o >>= 1) pn2 += __shfl_xor_sync(0xffffffffu, pn2, o);
    float npn = fmaxf(sqrtf(pn2), EPSc);
    float t2  = fminf(fmaxf(SCc*npn, EPSc), 1.f - 1e-6f);
    float cf  = atanhf(t2) / (SCc*npn);
    float v0 = cf*p0, v1 = cf*p1, v2 = cf*p2, v3 = cf*p3;

    // logits
    for (int k = 0; k < NCd; k++) {
        float4 w = *(const float4*)(Wf + (size_t)k*Dd + lane*4);
        float pr = v0*w.x + v1*w.y + v2*w.z + v3*w.w;
        #pragma unroll
        for (int o = 16; o; o >>= 1) pr += __shfl_xor_sync(0xffffffffu, pr, o);
        if (lane == 0) out[b*NCd + k] = pr + bf[k];
    }
}

// ---------------------------- launcher -------------------------------------
extern "C" void kernel_launch(void* const* d_in, const int* in_sizes, int n_in,
                              void* d_out, int out_size)
{
    (void)in_sizes; (void)n_in; (void)out_size;
    const int*   tok  = (const int*)d_in[0];
    const void*  mask = d_in[1];
    const float* emb  = (const float*)d_in[2];
    const float* Wo   = (const float*)d_in[3];
    const float* bo   = (const float*)d_in[4];
    const float* Wf   = (const float*)d_in[5];
    const float* bf   = (const float*)d_in[6];
    float*       out  = (float*)d_out;

    cudaFuncSetAttribute(k_attn_mma, cudaFuncAttributeMaxDynamicSharedMemorySize, ATT_SMEM);

    k_detect   <<<1, 1024>>>((const uint4*)mask);
    k_prep     <<<256 + (Dd*Dd + 255)/256, 256>>>(mask, Wo);
    k_embed    <<<(Bd*Nd)/8, 256>>>(tok, emb);
    k_attn_mma <<<dim3(16, Bd), 128, ATT_SMEM>>>(bo);
    k_pairdot  <<<Bd*16, 128>>>();
    k_pool     <<<Bd, 32>>>(Wf, bf, out);
}